// round 1
// baseline (speedup 1.0000x reference)
#include <cuda_runtime.h>
#include <math.h>

// Problem constants
#define B_SZ 256
#define T_SZ 96
#define F_DIM 368
#define D_MODEL 368
#define G3 1104          // 3*D_MODEL
#define NCLS 29
#define NOUT 31          // 2 coarse + 29 fine
#define M_ROWS 24576     // B*T

// -------- device scratch (static __device__ arrays; no allocation) --------
__device__ float g_xproj[(size_t)M_ROWS * G3];      // (B*T, 3D)  ~108.5 MB
__device__ float g_temporal[(size_t)M_ROWS * D_MODEL]; // (B*T, D) ~36 MB
__device__ float g_logits[(size_t)M_ROWS * NOUT];   // (B*T, 31)  ~3 MB

// ============================================================
// Kernel 1: xproj = features @ Wi^T + bi   (M=24576, N=1104, K=368)
// BM=128 BN=64 BK=16, 256 threads, thread tile 8x4
// ============================================================
__global__ void xproj_kernel(const float* __restrict__ A,
                             const float* __restrict__ W,
                             const float* __restrict__ bi)
{
    __shared__ float As[16][128];
    __shared__ float Bs[16][64];

    const int m0 = blockIdx.y * 128;
    const int n0 = blockIdx.x * 64;
    const int tid = threadIdx.x;
    const int tx = tid & 15;        // 0..15 -> 4 cols each
    const int ty = tid >> 4;        // 0..15 -> 8 rows each

    float acc[8][4];
#pragma unroll
    for (int i = 0; i < 8; i++)
#pragma unroll
        for (int j = 0; j < 4; j++) acc[i][j] = 0.f;

    for (int k0 = 0; k0 < F_DIM; k0 += 16) {
        // A tile: 128 rows x 16 k = 512 float4, 2 per thread (transposed store)
#pragma unroll
        for (int l = 0; l < 2; l++) {
            int idx = tid + l * 256;
            int row = idx >> 2, kq = idx & 3;
            float4 v = *(const float4*)(A + (size_t)(m0 + row) * F_DIM + k0 + kq * 4);
            As[kq * 4 + 0][row] = v.x;
            As[kq * 4 + 1][row] = v.y;
            As[kq * 4 + 2][row] = v.z;
            As[kq * 4 + 3][row] = v.w;
        }
        // B tile: 64 rows x 16 k = 256 float4, 1 per thread
        {
            int row = tid >> 2, kq = tid & 3;
            int n = n0 + row;
            float4 v = make_float4(0.f, 0.f, 0.f, 0.f);
            if (n < G3)
                v = *(const float4*)(W + (size_t)n * F_DIM + k0 + kq * 4);
            Bs[kq * 4 + 0][row] = v.x;
            Bs[kq * 4 + 1][row] = v.y;
            Bs[kq * 4 + 2][row] = v.z;
            Bs[kq * 4 + 3][row] = v.w;
        }
        __syncthreads();
#pragma unroll
        for (int k = 0; k < 16; k++) {
            float a[8], b[4];
#pragma unroll
            for (int i = 0; i < 8; i++) a[i] = As[k][ty * 8 + i];
#pragma unroll
            for (int j = 0; j < 4; j++) b[j] = Bs[k][tx * 4 + j];
#pragma unroll
            for (int i = 0; i < 8; i++)
#pragma unroll
                for (int j = 0; j < 4; j++) acc[i][j] += a[i] * b[j];
        }
        __syncthreads();
    }

    float bv[4];
#pragma unroll
    for (int j = 0; j < 4; j++) {
        int n = n0 + tx * 4 + j;
        bv[j] = (n < G3) ? bi[n] : 0.f;
    }
#pragma unroll
    for (int i = 0; i < 8; i++) {
        int m = m0 + ty * 8 + i;
#pragma unroll
        for (int j = 0; j < 4; j++) {
            int n = n0 + tx * 4 + j;
            if (n < G3) g_xproj[(size_t)m * G3 + n] = acc[i][j] + bv[j];
        }
    }
}

// ============================================================
// Kernel 2: one GRU time step.
// grid = 128 blocks = 8 batch-groups(32) x 16 unit-groups(24, padded to 384)
// 128 threads. warp = 32 batches (lane = batch), warp q owns units {q,q+4,...,q+20}
// smem: wh_s[72][369] + h_s[32][369]  (369 pad -> conflict-free)
// ============================================================
#define GRU_SMEM ((72 * 369 + 32 * 369) * 4)

__global__ void gru_step_kernel(const float* __restrict__ Wh,
                                const float* __restrict__ bh,
                                int t)
{
    extern __shared__ float sm[];
    float* wh_s = sm;              // [72][369]
    float* h_s  = sm + 72 * 369;   // [32][369]

    const int bx = blockIdx.x;
    const int bg = bx & 7;
    const int ug = bx >> 3;
    const int b0 = bg * 32;
    const int d0 = ug * 24;
    const int tid = threadIdx.x;

    // load Wh rows (3 gates x 24 units) into smem, rows padded to 369
    for (int idx = tid; idx < 72 * 92; idx += 128) {
        int row = idx / 92, kq = idx % 92;
        int g = row / 24, u = row - g * 24;
        int d = d0 + u;
        float4 v = make_float4(0.f, 0.f, 0.f, 0.f);
        if (d < D_MODEL)
            v = *(const float4*)(Wh + (size_t)(g * D_MODEL + d) * D_MODEL + kq * 4);
        float* dst = wh_s + row * 369 + kq * 4;
        dst[0] = v.x; dst[1] = v.y; dst[2] = v.z; dst[3] = v.w;
    }
    // load h_{t-1} tile (32 batches x 368)
    if (t > 0) {
        for (int idx = tid; idx < 32 * 92; idx += 128) {
            int row = idx / 92, kq = idx % 92;
            float4 v = *(const float4*)(g_temporal +
                        ((size_t)(b0 + row) * T_SZ + (t - 1)) * D_MODEL + kq * 4);
            float* dst = h_s + row * 369 + kq * 4;
            dst[0] = v.x; dst[1] = v.y; dst[2] = v.z; dst[3] = v.w;
        }
    }
    __syncthreads();

    const int bl = tid & 31;   // batch lane
    const int q  = tid >> 5;   // warp id 0..3

    float acc[6][3];
#pragma unroll
    for (int i = 0; i < 6; i++)
#pragma unroll
        for (int g = 0; g < 3; g++) acc[i][g] = 0.f;

    if (t > 0) {
        const float* hrow = h_s + bl * 369;
        // base offsets for the 18 rows this thread reads (broadcast in-warp)
#pragma unroll 8
        for (int k = 0; k < D_MODEL; k++) {
            float hv = hrow[k];
#pragma unroll
            for (int i = 0; i < 6; i++) {
                int u = q + 4 * i;
#pragma unroll
                for (int g = 0; g < 3; g++)
                    acc[i][g] += hv * wh_s[(g * 24 + u) * 369 + k];
            }
        }
    }

    const int b = b0 + bl;
    const size_t xbase = ((size_t)b * T_SZ + t) * G3;
    const size_t obase = ((size_t)b * T_SZ + t) * D_MODEL;
#pragma unroll
    for (int i = 0; i < 6; i++) {
        int d = d0 + q + 4 * i;
        if (d < D_MODEL) {
            float ghr = acc[i][0] + bh[d];
            float ghz = acc[i][1] + bh[D_MODEL + d];
            float ghn = acc[i][2] + bh[2 * D_MODEL + d];
            float gir = g_xproj[xbase + d];
            float giz = g_xproj[xbase + D_MODEL + d];
            float gin = g_xproj[xbase + 2 * D_MODEL + d];
            float r = 1.f / (1.f + expf(-(gir + ghr)));
            float z = 1.f / (1.f + expf(-(giz + ghz)));
            float n = tanhf(gin + r * ghn);
            float hp = (t > 0) ? h_s[bl * 369 + d] : 0.f;
            g_temporal[obase + d] = (1.f - z) * n + z * hp;
        }
    }
}

// ============================================================
// Kernel 3: logits = temporal @ [Wc;Wf]^T + [bc;bf]
// 96 blocks x 128 threads, 256 rows/block, 2 rows/thread, all 31 W rows in smem
// ============================================================
#define HEAD_SMEM ((31 * 368 + 256 * 93) * 4)

__global__ void head_kernel(const float* __restrict__ Wc,
                            const float* __restrict__ bc,
                            const float* __restrict__ Wf,
                            const float* __restrict__ bf)
{
    extern __shared__ float sm[];
    float* W_s = sm;               // [31][368]
    float* A_s = sm + 31 * 368;    // [256][93] (padded)

    const int m0 = blockIdx.x * 256;
    const int tid = threadIdx.x;

    // stage all head weights
    for (int idx = tid; idx < 31 * 92; idx += 128) {
        int row = idx / 92, kq = idx % 92;
        const float* src = (row < 2) ? (Wc + (size_t)row * D_MODEL)
                                     : (Wf + (size_t)(row - 2) * D_MODEL);
        float4 v = *(const float4*)(src + kq * 4);
        *(float4*)(W_s + row * D_MODEL + kq * 4) = v;
    }

    float acc0[NOUT], acc1[NOUT];
#pragma unroll
    for (int o = 0; o < NOUT; o++) { acc0[o] = 0.f; acc1[o] = 0.f; }

    for (int c = 0; c < 4; c++) {     // K chunks of 92
        __syncthreads();
        for (int idx = tid; idx < 256 * 23; idx += 128) {
            int row = idx / 23, kq = idx % 23;
            float4 v = *(const float4*)(g_temporal +
                         (size_t)(m0 + row) * D_MODEL + c * 92 + kq * 4);
            float* dst = A_s + row * 93 + kq * 4;
            dst[0] = v.x; dst[1] = v.y; dst[2] = v.z; dst[3] = v.w;
        }
        __syncthreads();
#pragma unroll 4
        for (int k = 0; k < 92; k++) {
            float a0 = A_s[tid * 93 + k];
            float a1 = A_s[(tid + 128) * 93 + k];
#pragma unroll
            for (int o = 0; o < NOUT; o++) {
                float w = W_s[o * D_MODEL + c * 92 + k];
                acc0[o] += a0 * w;
                acc1[o] += a1 * w;
            }
        }
    }

#pragma unroll
    for (int o = 0; o < NOUT; o++) {
        float bias = (o < 2) ? bc[o] : bf[o - 2];
        g_logits[(size_t)(m0 + tid) * NOUT + o] = acc0[o] + bias;
        g_logits[(size_t)(m0 + tid + 128) * NOUT + o] = acc1[o] + bias;
    }
}

// ============================================================
// Kernel 4: softmax + sigmoid + NMS + argmax, write concatenated output:
// out[0:24576)            coarse_decisions (as float 0/1)
// out[24576 : 24576+49152) coarse_nms (B,T,2)
// out[24576*3 : )          fine_scores (B,T,29)
// block per batch (256), thread per t (96)
// ============================================================
__global__ void finalize_kernel(float* __restrict__ out)
{
    __shared__ float bg_s[T_SZ];
    const int b = blockIdx.x;
    const int t = threadIdx.x;
    const size_t mi = (size_t)b * T_SZ + t;
    const float* L = g_logits + mi * NOUT;

    float l0 = L[0], l1 = L[1];
    float mx = fmaxf(l0, l1);
    float e0 = expf(l0 - mx), e1 = expf(l1 - mx);
    float inv = 1.f / (e0 + e1);
    float s0 = e0 * inv, s1 = e1 * inv;
    bg_s[t] = s0;

#pragma unroll
    for (int j = 0; j < NCLS; j++) {
        float v = 1.f / (1.f + expf(-L[2 + j]));
        out[(size_t)M_ROWS * 3 + mi * NCLS + j] = v;
    }
    __syncthreads();

    float wmin = s0;
#pragma unroll
    for (int dt = -2; dt <= 2; dt++) {
        int tt = t + dt;
        if (tt >= 0 && tt < T_SZ) wmin = fminf(wmin, bg_s[tt]);
    }
    bool keep = (s0 == wmin);
    float n0 = keep ? s0 : 0.f;
    float n1 = keep ? s1 : 0.f;

    out[mi] = (n1 > n0) ? 1.f : 0.f;
    out[M_ROWS + mi * 2 + 0] = n0;
    out[M_ROWS + mi * 2 + 1] = n1;
}

// ============================================================
extern "C" void kernel_launch(void* const* d_in, const int* in_sizes, int n_in,
                              void* d_out, int out_size)
{
    const float* features = (const float*)d_in[0];
    // d_in[1] = hand (unused, matches reference)
    const float* Wi = (const float*)d_in[2];
    const float* Wh = (const float*)d_in[3];
    const float* bi = (const float*)d_in[4];
    const float* bh = (const float*)d_in[5];
    const float* Wc = (const float*)d_in[6];
    const float* bc = (const float*)d_in[7];
    const float* Wf = (const float*)d_in[8];
    const float* bf = (const float*)d_in[9];
    float* out = (float*)d_out;

    cudaFuncSetAttribute(gru_step_kernel,
                         cudaFuncAttributeMaxDynamicSharedMemorySize, GRU_SMEM);
    cudaFuncSetAttribute(head_kernel,
                         cudaFuncAttributeMaxDynamicSharedMemorySize, HEAD_SMEM);

    // 1) input projection
    dim3 xg((G3 + 63) / 64, M_ROWS / 128);
    xproj_kernel<<<xg, 256>>>(features, Wi, bi);

    // 2) recurrence: 96 sequential steps
    for (int t = 0; t < T_SZ; t++)
        gru_step_kernel<<<128, 128, GRU_SMEM>>>(Wh, bh, t);

    // 3) output heads
    head_kernel<<<M_ROWS / 256, 128, HEAD_SMEM>>>(Wc, bc, Wf, bf);

    // 4) softmax/sigmoid/NMS/argmax + writes
    finalize_kernel<<<B_SZ, T_SZ>>>(out);
}

// round 2
// speedup vs baseline: 1.4600x; 1.4600x over previous
#include <cuda_runtime.h>
#include <math.h>

// Problem constants
#define B_SZ 256
#define T_SZ 96
#define F_DIM 368
#define D_MODEL 368
#define G3 1104          // 3*D_MODEL
#define NCLS 29
#define NOUT 31          // 2 coarse + 29 fine
#define M_ROWS 24576     // B*T

// -------- device scratch (static __device__ arrays; no allocation) --------
__device__ float g_xproj[(size_t)M_ROWS * G3];                 // (B*T, 3D)
__device__ float g_xprojT[(size_t)T_SZ * D_MODEL * 3 * B_SZ];  // [t][u][g][b]
__device__ float g_h[(size_t)T_SZ * D_MODEL * B_SZ];           // [t][d][b]
__device__ float g_temporal[(size_t)M_ROWS * D_MODEL];         // (B*T, D)
__device__ float g_logits[(size_t)M_ROWS * NOUT];

// ============================================================
// Kernel 1: xproj = features @ Wi^T + bi   (M=24576, N=1104, K=368)
// BM=128 BN=64 BK=16, 256 threads, thread tile 8x4  (unchanged)
// ============================================================
__global__ void xproj_kernel(const float* __restrict__ A,
                             const float* __restrict__ W,
                             const float* __restrict__ bi)
{
    __shared__ float As[16][128];
    __shared__ float Bs[16][64];

    const int m0 = blockIdx.y * 128;
    const int n0 = blockIdx.x * 64;
    const int tid = threadIdx.x;
    const int tx = tid & 15;
    const int ty = tid >> 4;

    float acc[8][4];
#pragma unroll
    for (int i = 0; i < 8; i++)
#pragma unroll
        for (int j = 0; j < 4; j++) acc[i][j] = 0.f;

    for (int k0 = 0; k0 < F_DIM; k0 += 16) {
#pragma unroll
        for (int l = 0; l < 2; l++) {
            int idx = tid + l * 256;
            int row = idx >> 2, kq = idx & 3;
            float4 v = *(const float4*)(A + (size_t)(m0 + row) * F_DIM + k0 + kq * 4);
            As[kq * 4 + 0][row] = v.x;
            As[kq * 4 + 1][row] = v.y;
            As[kq * 4 + 2][row] = v.z;
            As[kq * 4 + 3][row] = v.w;
        }
        {
            int row = tid >> 2, kq = tid & 3;
            int n = n0 + row;
            float4 v = make_float4(0.f, 0.f, 0.f, 0.f);
            if (n < G3)
                v = *(const float4*)(W + (size_t)n * F_DIM + k0 + kq * 4);
            Bs[kq * 4 + 0][row] = v.x;
            Bs[kq * 4 + 1][row] = v.y;
            Bs[kq * 4 + 2][row] = v.z;
            Bs[kq * 4 + 3][row] = v.w;
        }
        __syncthreads();
#pragma unroll
        for (int k = 0; k < 16; k++) {
            float a[8], b[4];
#pragma unroll
            for (int i = 0; i < 8; i++) a[i] = As[k][ty * 8 + i];
#pragma unroll
            for (int j = 0; j < 4; j++) b[j] = Bs[k][tx * 4 + j];
#pragma unroll
            for (int i = 0; i < 8; i++)
#pragma unroll
                for (int j = 0; j < 4; j++) acc[i][j] += a[i] * b[j];
        }
        __syncthreads();
    }

    float bv[4];
#pragma unroll
    for (int j = 0; j < 4; j++) {
        int n = n0 + tx * 4 + j;
        bv[j] = (n < G3) ? bi[n] : 0.f;
    }
#pragma unroll
    for (int i = 0; i < 8; i++) {
        int m = m0 + ty * 8 + i;
#pragma unroll
        for (int j = 0; j < 4; j++) {
            int n = n0 + tx * 4 + j;
            if (n < G3) g_xproj[(size_t)m * G3 + n] = acc[i][j] + bv[j];
        }
    }
}

// ============================================================
// Kernel 1b: transpose xproj (b,t,g,u) -> xprojT [t][u][g][b]
// grid (96, 12, 8), block (32, 8)
// ============================================================
__global__ void xprojT_kernel()
{
    __shared__ float tile[32][33];
    const int t = blockIdx.x;
    const int u0 = blockIdx.y * 32;
    const int b0 = blockIdx.z * 32;
    const int tx = threadIdx.x, ty = threadIdx.y;

    for (int g = 0; g < 3; g++) {
        for (int bb = ty; bb < 32; bb += 8) {
            int u = u0 + tx;
            float v = 0.f;
            if (u < D_MODEL)
                v = g_xproj[((size_t)(b0 + bb) * T_SZ + t) * G3 + g * D_MODEL + u];
            tile[tx][bb] = v;   // tile[u][b]
        }
        __syncthreads();
        for (int ur = ty; ur < 32; ur += 8) {
            int u = u0 + ur;
            if (u < D_MODEL)
                g_xprojT[(((size_t)t * D_MODEL + u) * 3 + g) * B_SZ + b0 + tx] = tile[ur][tx];
        }
        __syncthreads();
    }
}

// ============================================================
// Kernel 2: one GRU time step (restructured).
// grid = 128 = 16 unit-groups(23 units) x 8 batch-groups(32 batches)
// 128 threads: tid = tu*16 + tb;  tu in [0,8) (3 units each), tb in [0,16) (2 batches)
// thread tile: 3 units x 3 gates x 2 batches = 18 FFMA per k, 10 LDS per k.
// smem: wh_s[72][368] row=(ul*3+g), + h_s[368][36] (all units, 32 batches)
// ============================================================
#define WH_STRIDE 368
#define HS_STRIDE 36
#define GRU_SMEM ((72 * WH_STRIDE + D_MODEL * HS_STRIDE) * 4)

__global__ __launch_bounds__(128, 1)
void gru_step_kernel(const float* __restrict__ Wh,
                     const float* __restrict__ bh, int t)
{
    extern __shared__ float sm[];
    float* wh_s = sm;                      // [72][368]
    float* h_s  = sm + 72 * WH_STRIDE;     // [368][36]

    const int tid = threadIdx.x;
    const int bg = blockIdx.x & 7;
    const int ug = blockIdx.x >> 3;
    const int b0 = bg * 32;
    const int u0 = ug * 23;
    const int tu = tid >> 4;   // 0..7
    const int tb = tid & 15;   // 0..15

    // fill wh_s: straight [row][k] copy, rows = (ul*3+g), ul<23 real, 23 = pad
    for (int idx = tid; idx < 72 * 92; idx += 128) {
        int r = idx / 92, q = idx - r * 92;
        int ul = r / 3, g = r - ul * 3;
        float4 v = make_float4(0.f, 0.f, 0.f, 0.f);
        if (ul < 23)
            v = *(const float4*)(Wh + ((size_t)(g * D_MODEL + u0 + ul)) * D_MODEL + q * 4);
        *(float4*)(wh_s + r * WH_STRIDE + q * 4) = v;
    }
    // fill h_s: coalesced copy of h_{t-1}[all 368 units][our 32 batches]
    if (t > 0) {
        const float* hp = g_h + (size_t)(t - 1) * D_MODEL * B_SZ;
        for (int idx = tid; idx < D_MODEL * 8; idx += 128) {
            int u = idx >> 3, c = idx & 7;
            float4 v = *(const float4*)(hp + (size_t)u * B_SZ + b0 + c * 4);
            *(float4*)(h_s + u * HS_STRIDE + c * 4) = v;
        }
    }
    __syncthreads();

    float acc[3][3][2];
#pragma unroll
    for (int j = 0; j < 3; j++)
#pragma unroll
        for (int g = 0; g < 3; g++) { acc[j][g][0] = 0.f; acc[j][g][1] = 0.f; }

    if (t > 0) {
#pragma unroll 4
        for (int k = 0; k < D_MODEL; k++) {
            float2 hv = *(const float2*)(h_s + k * HS_STRIDE + tb * 2);
#pragma unroll
            for (int j = 0; j < 3; j++) {
#pragma unroll
                for (int g = 0; g < 3; g++) {
                    float w = wh_s[((tu * 3 + j) * 3 + g) * WH_STRIDE + k];
                    acc[j][g][0] += w * hv.x;
                    acc[j][g][1] += w * hv.y;
                }
            }
        }
    }

    // gate math + write h_t to g_h[t][d][b]
    const float* xT = g_xprojT + (size_t)t * D_MODEL * 3 * B_SZ;
    float* hout = g_h + (size_t)t * D_MODEL * B_SZ;
#pragma unroll
    for (int j = 0; j < 3; j++) {
        int ul = tu * 3 + j;
        if (ul < 23) {
            int d = u0 + ul;
            float bhr = bh[d];
            float bhz = bh[D_MODEL + d];
            float bhn = bh[2 * D_MODEL + d];
#pragma unroll
            for (int bb = 0; bb < 2; bb++) {
                int b = b0 + tb * 2 + bb;
                float gir = xT[((size_t)d * 3 + 0) * B_SZ + b];
                float giz = xT[((size_t)d * 3 + 1) * B_SZ + b];
                float gin = xT[((size_t)d * 3 + 2) * B_SZ + b];
                float rr = 1.f / (1.f + expf(-(gir + acc[j][0][bb] + bhr)));
                float zz = 1.f / (1.f + expf(-(giz + acc[j][1][bb] + bhz)));
                float nn = tanhf(gin + rr * (acc[j][2][bb] + bhn));
                float hprev = (t > 0) ? h_s[d * HS_STRIDE + tb * 2 + bb] : 0.f;
                hout[(size_t)d * B_SZ + b] = (1.f - zz) * nn + zz * hprev;
            }
        }
    }
}

// ============================================================
// Kernel 2b: transpose g_h [t][d][b] -> g_temporal (b,t,d)
// grid (96, 12, 8), block (32, 8)
// ============================================================
__global__ void hT_kernel()
{
    __shared__ float tile[32][33];
    const int t = blockIdx.x;
    const int d0 = blockIdx.y * 32;
    const int b0 = blockIdx.z * 32;
    const int tx = threadIdx.x, ty = threadIdx.y;

    for (int dr = ty; dr < 32; dr += 8) {
        int d = d0 + dr;
        float v = 0.f;
        if (d < D_MODEL)
            v = g_h[((size_t)t * D_MODEL + d) * B_SZ + b0 + tx];
        tile[dr][tx] = v;
    }
    __syncthreads();
    for (int br = ty; br < 32; br += 8) {
        int d = d0 + tx;
        if (d < D_MODEL)
            g_temporal[((size_t)(b0 + br) * T_SZ + t) * D_MODEL + d] = tile[tx][br];
    }
}

// ============================================================
// Kernel 3: logits = temporal @ [Wc;Wf]^T + [bc;bf]  (unchanged)
// ============================================================
#define HEAD_SMEM ((31 * 368 + 256 * 93) * 4)

__global__ void head_kernel(const float* __restrict__ Wc,
                            const float* __restrict__ bc,
                            const float* __restrict__ Wf,
                            const float* __restrict__ bf)
{
    extern __shared__ float sm[];
    float* W_s = sm;               // [31][368]
    float* A_s = sm + 31 * 368;    // [256][93]

    const int m0 = blockIdx.x * 256;
    const int tid = threadIdx.x;

    for (int idx = tid; idx < 31 * 92; idx += 128) {
        int row = idx / 92, kq = idx % 92;
        const float* src = (row < 2) ? (Wc + (size_t)row * D_MODEL)
                                     : (Wf + (size_t)(row - 2) * D_MODEL);
        float4 v = *(const float4*)(src + kq * 4);
        *(float4*)(W_s + row * D_MODEL + kq * 4) = v;
    }

    float acc0[NOUT], acc1[NOUT];
#pragma unroll
    for (int o = 0; o < NOUT; o++) { acc0[o] = 0.f; acc1[o] = 0.f; }

    for (int c = 0; c < 4; c++) {
        __syncthreads();
        for (int idx = tid; idx < 256 * 23; idx += 128) {
            int row = idx / 23, kq = idx % 23;
            float4 v = *(const float4*)(g_temporal +
                         (size_t)(m0 + row) * D_MODEL + c * 92 + kq * 4);
            float* dst = A_s + row * 93 + kq * 4;
            dst[0] = v.x; dst[1] = v.y; dst[2] = v.z; dst[3] = v.w;
        }
        __syncthreads();
#pragma unroll 4
        for (int k = 0; k < 92; k++) {
            float a0 = A_s[tid * 93 + k];
            float a1 = A_s[(tid + 128) * 93 + k];
#pragma unroll
            for (int o = 0; o < NOUT; o++) {
                float w = W_s[o * D_MODEL + c * 92 + k];
                acc0[o] += a0 * w;
                acc1[o] += a1 * w;
            }
        }
    }

#pragma unroll
    for (int o = 0; o < NOUT; o++) {
        float bias = (o < 2) ? bc[o] : bf[o - 2];
        g_logits[(size_t)(m0 + tid) * NOUT + o] = acc0[o] + bias;
        g_logits[(size_t)(m0 + tid + 128) * NOUT + o] = acc1[o] + bias;
    }
}

// ============================================================
// Kernel 4: softmax + sigmoid + NMS + argmax (unchanged)
// ============================================================
__global__ void finalize_kernel(float* __restrict__ out)
{
    __shared__ float bg_s[T_SZ];
    const int b = blockIdx.x;
    const int t = threadIdx.x;
    const size_t mi = (size_t)b * T_SZ + t;
    const float* L = g_logits + mi * NOUT;

    float l0 = L[0], l1 = L[1];
    float mx = fmaxf(l0, l1);
    float e0 = expf(l0 - mx), e1 = expf(l1 - mx);
    float inv = 1.f / (e0 + e1);
    float s0 = e0 * inv, s1 = e1 * inv;
    bg_s[t] = s0;

#pragma unroll
    for (int j = 0; j < NCLS; j++) {
        float v = 1.f / (1.f + expf(-L[2 + j]));
        out[(size_t)M_ROWS * 3 + mi * NCLS + j] = v;
    }
    __syncthreads();

    float wmin = s0;
#pragma unroll
    for (int dt = -2; dt <= 2; dt++) {
        int tt = t + dt;
        if (tt >= 0 && tt < T_SZ) wmin = fminf(wmin, bg_s[tt]);
    }
    bool keep = (s0 == wmin);
    float n0 = keep ? s0 : 0.f;
    float n1 = keep ? s1 : 0.f;

    out[mi] = (n1 > n0) ? 1.f : 0.f;
    out[M_ROWS + mi * 2 + 0] = n0;
    out[M_ROWS + mi * 2 + 1] = n1;
}

// ============================================================
extern "C" void kernel_launch(void* const* d_in, const int* in_sizes, int n_in,
                              void* d_out, int out_size)
{
    const float* features = (const float*)d_in[0];
    // d_in[1] = hand (unused)
    const float* Wi = (const float*)d_in[2];
    const float* Wh = (const float*)d_in[3];
    const float* bi = (const float*)d_in[4];
    const float* bh = (const float*)d_in[5];
    const float* Wc = (const float*)d_in[6];
    const float* bc = (const float*)d_in[7];
    const float* Wf = (const float*)d_in[8];
    const float* bf = (const float*)d_in[9];
    float* out = (float*)d_out;

    cudaFuncSetAttribute(gru_step_kernel,
                         cudaFuncAttributeMaxDynamicSharedMemorySize, GRU_SMEM);
    cudaFuncSetAttribute(head_kernel,
                         cudaFuncAttributeMaxDynamicSharedMemorySize, HEAD_SMEM);

    // 1) input projection + transpose to [t][u][g][b]
    dim3 xg((G3 + 63) / 64, M_ROWS / 128);
    xproj_kernel<<<xg, 256>>>(features, Wi, bi);
    xprojT_kernel<<<dim3(T_SZ, 12, 8), dim3(32, 8)>>>();

    // 2) recurrence: 96 sequential steps
    for (int t = 0; t < T_SZ; t++)
        gru_step_kernel<<<128, 128, GRU_SMEM>>>(Wh, bh, t);

    // 2b) transpose hidden states to (b,t,d) for heads
    hT_kernel<<<dim3(T_SZ, 12, 8), dim3(32, 8)>>>();

    // 3) output heads
    head_kernel<<<M_ROWS / 256, 128, HEAD_SMEM>>>(Wc, bc, Wf, bf);

    // 4) softmax/sigmoid/NMS/argmax
    finalize_kernel<<<B_SZ, T_SZ>>>(out);
}